// round 1
// baseline (speedup 1.0000x reference)
#include <cuda_runtime.h>
#include <cstdint>

// Problem constants
#define Bq 8
#define Nq 2048
#define Dq 256
#define Kq 8192
#define Mq (Bq * Nq)   // 16384

// Tiling for the distance kernel
#define TM 64
#define TK 64
#define DCH 16
#define KSPLIT 4

// Scratch (no cudaMalloc allowed): packed (order-preserving-dist | index) per row, and ||c||^2
__device__ unsigned long long g_best[Mq];
__device__ float g_c2[Kq];

// Order-preserving float -> uint mapping (ascending float order == ascending uint order)
__device__ __forceinline__ unsigned int fkey(float f) {
    unsigned int u = __float_as_uint(f);
    return (u & 0x80000000u) ? ~u : (u | 0x80000000u);
}

// ---------------------------------------------------------------------------
// Kernel 1: c2[k] = ||codebook[k]||^2  (one warp per code) + init g_best.
// Must run every launch (graph replays reuse g_best).
// ---------------------------------------------------------------------------
__global__ void prep_kernel(const float* __restrict__ cb) {
    int gtid = blockIdx.x * blockDim.x + threadIdx.x;
    int warp = gtid >> 5;
    int lane = gtid & 31;
    if (warp < Kq) {
        const float* row = cb + (size_t)warp * Dq;
        float s = 0.f;
        #pragma unroll
        for (int d = lane; d < Dq; d += 32) {
            float v = row[d];
            s += v * v;
        }
        #pragma unroll
        for (int o = 16; o; o >>= 1) s += __shfl_xor_sync(0xffffffffu, s, o);
        if (lane == 0) g_c2[warp] = s;
    }
    if (gtid < Mq) g_best[gtid] = 0xFFFFFFFFFFFFFFFFULL;
}

// ---------------------------------------------------------------------------
// Kernel 2: fused distance + argmin.
// Grid: (Mq/TM, KSPLIT). Each block: 64 rows x (Kq/KSPLIT) codes.
// 256 threads, each computes a 4x4 micro-tile of the cross product.
// dist(m,k) = c2[k] - 2 * dot(x[m], cb[k])   (row-constant ||x||^2 dropped)
// ---------------------------------------------------------------------------
__global__ __launch_bounds__(256) void dist_kernel(const float* __restrict__ x,
                                                   const float* __restrict__ cb) {
    __shared__ float xs[DCH][TM];
    __shared__ float cs[DCH][TK];

    const int m0  = blockIdx.x * TM;
    const int ks0 = blockIdx.y * (Kq / KSPLIT);
    const int tid = threadIdx.x;
    const int tx  = tid & 15;   // code sub-index
    const int ty  = tid >> 4;   // row sub-index

    float best[4];
    int   bidx[4];
    #pragma unroll
    for (int i = 0; i < 4; i++) { best[i] = __int_as_float(0x7f800000); bidx[i] = 0; }

    for (int kt = 0; kt < Kq / KSPLIT; kt += TK) {
        const int k0 = ks0 + kt;
        float acc[4][4];
        #pragma unroll
        for (int i = 0; i < 4; i++)
            #pragma unroll
            for (int j = 0; j < 4; j++) acc[i][j] = 0.f;

        for (int dc = 0; dc < Dq; dc += DCH) {
            __syncthreads();
            {
                const int r  = tid >> 2;          // 0..63
                const int d4 = (tid & 3) * 4;     // 0,4,8,12
                float4 vx = *(const float4*)(x  + (size_t)(m0 + r) * Dq + dc + d4);
                xs[d4 + 0][r] = vx.x; xs[d4 + 1][r] = vx.y;
                xs[d4 + 2][r] = vx.z; xs[d4 + 3][r] = vx.w;
                float4 vc = *(const float4*)(cb + (size_t)(k0 + r) * Dq + dc + d4);
                cs[d4 + 0][r] = vc.x; cs[d4 + 1][r] = vc.y;
                cs[d4 + 2][r] = vc.z; cs[d4 + 3][r] = vc.w;
            }
            __syncthreads();
            #pragma unroll
            for (int d = 0; d < DCH; d++) {
                float a[4], b[4];
                #pragma unroll
                for (int i = 0; i < 4; i++) a[i] = xs[d][ty + 16 * i];
                #pragma unroll
                for (int j = 0; j < 4; j++) b[j] = cs[d][tx + 16 * j];
                #pragma unroll
                for (int i = 0; i < 4; i++)
                    #pragma unroll
                    for (int j = 0; j < 4; j++) acc[i][j] += a[i] * b[j];
            }
        }

        // Fold this K-tile into per-row running argmin
        #pragma unroll
        for (int j = 0; j < 4; j++) {
            const int k = k0 + tx + 16 * j;
            const float c2 = g_c2[k];
            #pragma unroll
            for (int i = 0; i < 4; i++) {
                float dval = c2 - 2.f * acc[i][j];
                if (dval < best[i]) { best[i] = dval; bidx[i] = k; }
            }
        }
    }

    // Reduce across the 16 tx-lanes sharing each row (stays within a 16-lane half-warp)
    #pragma unroll
    for (int off = 8; off; off >>= 1) {
        #pragma unroll
        for (int i = 0; i < 4; i++) {
            float od = __shfl_xor_sync(0xffffffffu, best[i], off);
            int   oi = __shfl_xor_sync(0xffffffffu, bidx[i], off);
            if (od < best[i] || (od == best[i] && oi < bidx[i])) {
                best[i] = od; bidx[i] = oi;
            }
        }
    }
    if (tx == 0) {
        #pragma unroll
        for (int i = 0; i < 4; i++) {
            const int m = m0 + ty + 16 * i;
            unsigned long long packed =
                ((unsigned long long)fkey(best[i]) << 32) | (unsigned int)bidx[i];
            atomicMin(&g_best[m], packed);
        }
    }
}

// ---------------------------------------------------------------------------
// Kernel 3: gather + write tuple output:
//   out = [ x_recon (M*D) | z_e (M*D) | z_q (M*D) | indices-as-float (M) ]
// One block (64 threads, float4) per row.
// ---------------------------------------------------------------------------
__global__ void gather_kernel(const float* __restrict__ x,
                              const float* __restrict__ cb,
                              float* __restrict__ out) {
    const int m = blockIdx.x;
    const int idx = (int)(g_best[m] & 0xFFFFFFFFULL);

    const float4* crow = (const float4*)(cb + (size_t)idx * Dq);
    const float4* xrow = (const float4*)(x  + (size_t)m   * Dq);
    const size_t BND = (size_t)Mq * Dq;
    float4* o0 = (float4*)(out)             + (size_t)m * (Dq / 4);
    float4* o1 = (float4*)(out + BND)       + (size_t)m * (Dq / 4);
    float4* o2 = (float4*)(out + 2 * BND)   + (size_t)m * (Dq / 4);

    const int t = threadIdx.x;  // 0..63
    float4 c = crow[t];
    o0[t] = c;            // x_recon = z_q
    o2[t] = c;            // z_q
    o1[t] = xrow[t];      // z_e = x
    if (t == 0) out[3 * BND + m] = (float)idx;
}

// ---------------------------------------------------------------------------
extern "C" void kernel_launch(void* const* d_in, const int* in_sizes, int n_in,
                              void* d_out, int out_size) {
    const float* x  = (const float*)d_in[0];   // (B, N, D) fp32
    const float* cb = (const float*)d_in[1];   // (K, D) fp32
    float* out = (float*)d_out;
    (void)in_sizes; (void)n_in; (void)out_size;

    // c2 + best-init: 8192 warps needed -> 1024 blocks x 256 threads (also covers Mq init)
    prep_kernel<<<1024, 256>>>(cb);

    dim3 grid(Mq / TM, KSPLIT);
    dist_kernel<<<grid, 256>>>(x, cb);

    gather_kernel<<<Mq, 64>>>(x, cb, out);
}

// round 5
// speedup vs baseline: 3.3126x; 3.3126x over previous
#include <cuda_runtime.h>
#include <cuda_fp16.h>
#include <cstdint>

// Problem constants
#define Mq 16384   // B*N rows
#define Kq 8192    // codebook size
#define Dq 256     // dim
#define KP 1024    // K' = 4 * Dq (concat split: [hx,lx,hx,lx] . [hc,hc,lc,lc])

#define BM 128
#define BN 128
#define BK 64      // halves per k-iter (128 bytes per row-chunk)
#define NSTAGE 4
#define NITER (KP / BK)   // 16

// ---------------------------------------------------------------------------
// Static device scratch (no cudaMalloc allowed)
// ---------------------------------------------------------------------------
__device__ __align__(16) __half g_A[Mq * KP];   // 32 MB
__device__ __align__(16) __half g_B[Kq * KP];   // 16 MB
__device__ float g_c2[Kq];
__device__ unsigned long long g_best[Mq];

// ---------------------------------------------------------------------------
// Helpers
// ---------------------------------------------------------------------------
__device__ __forceinline__ unsigned int fkey(float f) {
    unsigned int u = __float_as_uint(f);
    return (u & 0x80000000u) ? ~u : (u | 0x80000000u);
}
__device__ __forceinline__ uint32_t smem_u32(const void* p) {
    uint32_t a;
    asm("{ .reg .u64 t; cvta.to.shared.u64 t, %1; cvt.u32.u64 %0, t; }" : "=r"(a) : "l"(p));
    return a;
}
#define CP_ASYNC16(dst, src) \
    asm volatile("cp.async.cg.shared.global [%0], [%1], 16;" :: "r"(dst), "l"(src))
#define CP_COMMIT() asm volatile("cp.async.commit_group;")
#define CP_WAIT(n)  asm volatile("cp.async.wait_group %0;" :: "n"(n))

#define LDMATRIX_X4(r0, r1, r2, r3, addr)                                     \
    asm volatile("ldmatrix.sync.aligned.m8n8.x4.shared.b16 {%0,%1,%2,%3}, [%4];" \
                 : "=r"(r0), "=r"(r1), "=r"(r2), "=r"(r3) : "r"(addr))

#define MMA16816(c, a, b0, b1)                                                \
    asm volatile(                                                             \
        "mma.sync.aligned.m16n8k16.row.col.f32.f16.f16.f32 "                  \
        "{%0,%1,%2,%3}, {%4,%5,%6,%7}, {%8,%9}, {%0,%1,%2,%3};"               \
        : "+f"((c)[0]), "+f"((c)[1]), "+f"((c)[2]), "+f"((c)[3])              \
        : "r"((a)[0]), "r"((a)[1]), "r"((a)[2]), "r"((a)[3]), "r"(b0), "r"(b1))

// ---------------------------------------------------------------------------
// Prep: split fp32 -> fp16 hi/lo, laid out as K'-concat rows.
// A'[m] = [hx(256) | lx | hx | lx],  B'[k] = [hc | hc | lc | lc]
// ---------------------------------------------------------------------------
__device__ __forceinline__ void split4(const float4 v, uint2& hp, uint2& lp) {
    float f[4] = {v.x, v.y, v.z, v.w};
    __half h[4], l[4];
#pragma unroll
    for (int j = 0; j < 4; j++) {
        h[j] = __float2half_rn(f[j]);
        l[j] = __float2half_rn(f[j] - __half2float(h[j]));
    }
    __half2 h01 = __halves2half2(h[0], h[1]), h23 = __halves2half2(h[2], h[3]);
    __half2 l01 = __halves2half2(l[0], l[1]), l23 = __halves2half2(l[2], l[3]);
    hp.x = *reinterpret_cast<uint32_t*>(&h01); hp.y = *reinterpret_cast<uint32_t*>(&h23);
    lp.x = *reinterpret_cast<uint32_t*>(&l01); lp.y = *reinterpret_cast<uint32_t*>(&l23);
}

__global__ void split_x_kernel(const float* __restrict__ x) {
    int i = blockIdx.x * 256 + threadIdx.x;      // over Mq*Dq/4
    int m = i >> 6, j = i & 63;                  // j: uint2 index within 256-half section
    uint2 hp, lp;
    split4(((const float4*)x)[i], hp, lp);
    uint2* pA = (uint2*)g_A + (size_t)m * 256;   // 1024 halves = 256 uint2 per row
    pA[j] = hp; pA[64 + j] = lp; pA[128 + j] = hp; pA[192 + j] = lp;
}

__global__ void split_c_kernel(const float* __restrict__ cb) {
    int i = blockIdx.x * 256 + threadIdx.x;      // over Kq*Dq/4
    int k = i >> 6, j = i & 63;
    uint2 hp, lp;
    split4(((const float4*)cb)[i], hp, lp);
    uint2* pB = (uint2*)g_B + (size_t)k * 256;
    pB[j] = hp; pB[64 + j] = hp; pB[128 + j] = lp; pB[192 + j] = lp;
}

// c2[k] = ||c_k||^2 (warp per code) + re-init g_best every launch (graph replay)
__global__ void prep_c2_kernel(const float* __restrict__ cb) {
    int gtid = blockIdx.x * blockDim.x + threadIdx.x;
    int warp = gtid >> 5, lane = gtid & 31;
    if (warp < Kq) {
        const float* row = cb + (size_t)warp * Dq;
        float s = 0.f;
#pragma unroll
        for (int d = lane; d < Dq; d += 32) { float v = row[d]; s += v * v; }
#pragma unroll
        for (int o = 16; o; o >>= 1) s += __shfl_xor_sync(0xffffffffu, s, o);
        if (lane == 0) g_c2[warp] = s;
    }
    if (gtid < Mq) g_best[gtid] = 0xFFFFFFFFFFFFFFFFULL;
}

// ---------------------------------------------------------------------------
// Fused GEMM (HMMA) + argmin.
// Grid (Mq/BM, Kq/BN) = (128, 64). 256 threads = 8 warps (4M x 2N).
// Warp tile 32M x 64N, mma m16n8k16.
// smem: NSTAGE stages of [A: 128x128B | B: 128x128B] = 32KB each, + c2 tile.
// ---------------------------------------------------------------------------
#define STAGE_BYTES 32768
#define SMEM_TOTAL (NSTAGE * STAGE_BYTES + 512)

__global__ __launch_bounds__(256, 1) void vq_mma_kernel() {
    extern __shared__ char smem[];
    const uint32_t sb = smem_u32(smem);
    const int tid = threadIdx.x;
    const int wid = tid >> 5, lane = tid & 31;
    const int m0 = blockIdx.x * BM, n0 = blockIdx.y * BN;
    const int wm = wid & 3, wn = wid >> 2;

    float* c2s = (float*)(smem + NSTAGE * STAGE_BYTES);
    if (tid < BN) c2s[tid] = g_c2[n0 + tid];

    // cp.async source/dst precompute: 2048 segs of 16B per stage (A:1024, B:1024)
    // thread handles 4 A segs + 4 B segs: e = tid + i*256; r=e>>3 (row), q=e&7 (seg)
    const char* gAb = (const char*)g_A;
    const char* gBb = (const char*)g_B;

    // ldmatrix row/seg components (swizzle: seg ^ (row & 7), row&7 == lane&7)
    const int rA = (lane & 7) + ((lane >> 3) & 1) * 8;   // A: row within 16
    const int sA = (lane >> 4) & 1;                      // A: k-seg select
    const int rB = (lane & 7) + ((lane >> 4) & 1) * 8;   // B: row within 16
    const int sB = (lane >> 3) & 1;                      // B: k-seg select
    const int l7 = lane & 7;

    uint32_t aoff[2], boff[4];
#pragma unroll
    for (int mi = 0; mi < 2; mi++) aoff[mi] = (wm * 32 + mi * 16 + rA) * 128;
#pragma unroll
    for (int nb = 0; nb < 4; nb++) boff[nb] = 16384 + (wn * 64 + nb * 16 + rB) * 128;

    float acc[2][8][4];
#pragma unroll
    for (int mi = 0; mi < 2; mi++)
#pragma unroll
        for (int nj = 0; nj < 8; nj++)
#pragma unroll
            for (int r = 0; r < 4; r++) acc[mi][nj][r] = 0.f;

    // ---- async load of one k-iter t into stage ----
    auto load_stage = [&](int t, int stage) {
        const uint32_t sAbase = sb + stage * STAGE_BYTES;
#pragma unroll
        for (int i = 0; i < 4; i++) {
            int e = tid + i * 256, r = e >> 3, q = e & 7;
            uint32_t dst = sAbase + r * 128 + ((q ^ (r & 7)) << 4);
            const char* src = gAb + (size_t)(m0 + r) * 2048 + t * 128 + q * 16;
            CP_ASYNC16(dst, src);
        }
#pragma unroll
        for (int i = 0; i < 4; i++) {
            int e = tid + i * 256, r = e >> 3, q = e & 7;
            uint32_t dst = sAbase + 16384 + r * 128 + ((q ^ (r & 7)) << 4);
            const char* src = gBb + (size_t)(n0 + r) * 2048 + t * 128 + q * 16;
            CP_ASYNC16(dst, src);
        }
        CP_COMMIT();
    };

    load_stage(0, 0);
    load_stage(1, 1);
    load_stage(2, 2);

    for (int t = 0; t < NITER; t++) {
        CP_WAIT(2);
        __syncthreads();
        if (t + 3 < NITER) load_stage(t + 3, (t + 3) & (NSTAGE - 1));

        const uint32_t st = sb + (t & (NSTAGE - 1)) * STAGE_BYTES;
#pragma unroll
        for (int ks = 0; ks < 4; ks++) {
            const uint32_t segA = (((ks * 2 + sA) ^ l7) << 4);
            const uint32_t segB = (((ks * 2 + sB) ^ l7) << 4);
            uint32_t a[2][4], b[4][4];
#pragma unroll
            for (int mi = 0; mi < 2; mi++)
                LDMATRIX_X4(a[mi][0], a[mi][1], a[mi][2], a[mi][3], st + aoff[mi] + segA);
#pragma unroll
            for (int nb = 0; nb < 4; nb++)
                LDMATRIX_X4(b[nb][0], b[nb][1], b[nb][2], b[nb][3], st + boff[nb] + segB);
#pragma unroll
            for (int mi = 0; mi < 2; mi++)
#pragma unroll
                for (int nj = 0; nj < 8; nj++)
                    MMA16816(acc[mi][nj], a[mi], b[nj >> 1][(nj & 1) * 2],
                             b[nj >> 1][(nj & 1) * 2 + 1]);
        }
    }

    // ---- fused argmin epilogue ----
    // acc[mi][nj] covers rows {wm*32+mi*16+lane/4, +8}, cols wn*64+nj*8+2*(lane&3)+{0,1}
#pragma unroll
    for (int mi = 0; mi < 2; mi++) {
#pragma unroll
        for (int h = 0; h < 2; h++) {
            float best = __int_as_float(0x7f800000);
            int bi = 0;
#pragma unroll
            for (int nj = 0; nj < 8; nj++) {
                int col = wn * 64 + nj * 8 + (lane & 3) * 2;
                float d0 = fmaf(-2.f, acc[mi][nj][h * 2 + 0], c2s[col]);
                float d1 = fmaf(-2.f, acc[mi][nj][h * 2 + 1], c2s[col + 1]);
                if (d0 < best) { best = d0; bi = col; }
                if (d1 < best) { best = d1; bi = col + 1; }
            }
            // reduce across the 4 lanes of the quad (same row)
#pragma unroll
            for (int off = 1; off <= 2; off <<= 1) {
                float od = __shfl_xor_sync(0xffffffffu, best, off);
                int oi = __shfl_xor_sync(0xffffffffu, bi, off);
                if (od < best || (od == best && oi < bi)) { best = od; bi = oi; }
            }
            if ((lane & 3) == 0) {
                int m = m0 + wm * 32 + mi * 16 + h * 8 + (lane >> 2);
                unsigned long long pk =
                    ((unsigned long long)fkey(best) << 32) | (unsigned int)(n0 + bi);
                atomicMin(&g_best[m], pk);
            }
        }
    }
}

// ---------------------------------------------------------------------------
// Gather + write tuple output: [x_recon | z_e | z_q | indices-as-float]
// ---------------------------------------------------------------------------
__global__ void gather_kernel(const float* __restrict__ x,
                              const float* __restrict__ cb,
                              float* __restrict__ out) {
    const int m = blockIdx.x;
    const int idx = (int)(g_best[m] & 0xFFFFFFFFULL);

    const float4* crow = (const float4*)(cb + (size_t)idx * Dq);
    const float4* xrow = (const float4*)(x + (size_t)m * Dq);
    const size_t BND = (size_t)Mq * Dq;
    float4* o0 = (float4*)(out) + (size_t)m * (Dq / 4);
    float4* o1 = (float4*)(out + BND) + (size_t)m * (Dq / 4);
    float4* o2 = (float4*)(out + 2 * BND) + (size_t)m * (Dq / 4);

    const int t = threadIdx.x;  // 0..63
    float4 c = crow[t];
    o0[t] = c;
    o2[t] = c;
    o1[t] = xrow[t];
    if (t == 0) out[3 * BND + m] = (float)idx;
}

// ---------------------------------------------------------------------------
extern "C" void kernel_launch(void* const* d_in, const int* in_sizes, int n_in,
                              void* d_out, int out_size) {
    const float* x = (const float*)d_in[0];    // (B, N, D) fp32
    const float* cb = (const float*)d_in[1];   // (K, D) fp32
    float* out = (float*)d_out;
    (void)in_sizes; (void)n_in; (void)out_size;

    split_x_kernel<<<Mq * Dq / 4 / 256, 256>>>(x);
    split_c_kernel<<<Kq * Dq / 4 / 256, 256>>>(cb);
    prep_c2_kernel<<<1024, 256>>>(cb);

    cudaFuncSetAttribute(vq_mma_kernel,
                         cudaFuncAttributeMaxDynamicSharedMemorySize, SMEM_TOTAL);
    dim3 grid(Mq / BM, Kq / BN);
    vq_mma_kernel<<<grid, 256, SMEM_TOTAL>>>();

    gather_kernel<<<Mq, 64>>>(x, cb, out);
}

// round 6
// speedup vs baseline: 4.2763x; 1.2909x over previous
#include <cuda_runtime.h>
#include <cuda_fp16.h>
#include <cstdint>

// Problem constants
#define Mq 16384   // B*N rows
#define Kq 8192    // codebook size
#define Dq 256     // dim
#define KP 1024    // K' = 4 * Dq (concat split: [hx,lx,hx,lx] . [hc,hc,lc,lc])

#define BM 128
#define BN 128
#define BK 64      // halves per k-iter (128 bytes per row-chunk)
#define NSTAGE 3
#define NITER (KP / BK)   // 16

// ---------------------------------------------------------------------------
// Static device scratch (no cudaMalloc allowed)
// ---------------------------------------------------------------------------
__device__ __align__(16) __half g_A[Mq * KP];   // 32 MB
__device__ __align__(16) __half g_B[Kq * KP];   // 16 MB
__device__ float g_c2[Kq];
__device__ unsigned long long g_best[Mq];

// ---------------------------------------------------------------------------
// Helpers
// ---------------------------------------------------------------------------
__device__ __forceinline__ unsigned int fkey(float f) {
    unsigned int u = __float_as_uint(f);
    return (u & 0x80000000u) ? ~u : (u | 0x80000000u);
}
__device__ __forceinline__ uint32_t smem_u32(const void* p) {
    uint32_t a;
    asm("{ .reg .u64 t; cvta.to.shared.u64 t, %1; cvt.u32.u64 %0, t; }" : "=r"(a) : "l"(p));
    return a;
}
#define CP_ASYNC16(dst, src) \
    asm volatile("cp.async.cg.shared.global [%0], [%1], 16;" :: "r"(dst), "l"(src))
#define CP_COMMIT() asm volatile("cp.async.commit_group;")
#define CP_WAIT(n)  asm volatile("cp.async.wait_group %0;" :: "n"(n))

#define LDMATRIX_X4(r0, r1, r2, r3, addr)                                     \
    asm volatile("ldmatrix.sync.aligned.m8n8.x4.shared.b16 {%0,%1,%2,%3}, [%4];" \
                 : "=r"(r0), "=r"(r1), "=r"(r2), "=r"(r3) : "r"(addr))

#define MMA16816(c, a, b0, b1)                                                \
    asm volatile(                                                             \
        "mma.sync.aligned.m16n8k16.row.col.f32.f16.f16.f32 "                  \
        "{%0,%1,%2,%3}, {%4,%5,%6,%7}, {%8,%9}, {%0,%1,%2,%3};"               \
        : "+f"((c)[0]), "+f"((c)[1]), "+f"((c)[2]), "+f"((c)[3])              \
        : "r"((a)[0]), "r"((a)[1]), "r"((a)[2]), "r"((a)[3]), "r"(b0), "r"(b1))

// ---------------------------------------------------------------------------
// Prep: split fp32 -> fp16 hi/lo, laid out as K'-concat rows.
// A'[m] = [hx(256) | lx | hx | lx],  B'[k] = [hc | hc | lc | lc]
// ---------------------------------------------------------------------------
__device__ __forceinline__ void split4(const float4 v, uint2& hp, uint2& lp) {
    float f[4] = {v.x, v.y, v.z, v.w};
    __half h[4], l[4];
#pragma unroll
    for (int j = 0; j < 4; j++) {
        h[j] = __float2half_rn(f[j]);
        l[j] = __float2half_rn(f[j] - __half2float(h[j]));
    }
    __half2 h01 = __halves2half2(h[0], h[1]), h23 = __halves2half2(h[2], h[3]);
    __half2 l01 = __halves2half2(l[0], l[1]), l23 = __halves2half2(l[2], l[3]);
    hp.x = *reinterpret_cast<uint32_t*>(&h01); hp.y = *reinterpret_cast<uint32_t*>(&h23);
    lp.x = *reinterpret_cast<uint32_t*>(&l01); lp.y = *reinterpret_cast<uint32_t*>(&l23);
}

__global__ void split_x_kernel(const float* __restrict__ x) {
    int i = blockIdx.x * 256 + threadIdx.x;      // over Mq*Dq/4
    int m = i >> 6, j = i & 63;                  // j: uint2 index within 256-half section
    uint2 hp, lp;
    split4(((const float4*)x)[i], hp, lp);
    uint2* pA = (uint2*)g_A + (size_t)m * 256;   // 1024 halves = 256 uint2 per row
    pA[j] = hp; pA[64 + j] = lp; pA[128 + j] = hp; pA[192 + j] = lp;
}

__global__ void split_c_kernel(const float* __restrict__ cb) {
    int i = blockIdx.x * 256 + threadIdx.x;      // over Kq*Dq/4
    int k = i >> 6, j = i & 63;
    uint2 hp, lp;
    split4(((const float4*)cb)[i], hp, lp);
    uint2* pB = (uint2*)g_B + (size_t)k * 256;
    pB[j] = hp; pB[64 + j] = hp; pB[128 + j] = lp; pB[192 + j] = lp;
}

// c2[k] = ||c_k||^2 (warp per code) + re-init g_best every launch (graph replay)
__global__ void prep_c2_kernel(const float* __restrict__ cb) {
    int gtid = blockIdx.x * blockDim.x + threadIdx.x;
    int warp = gtid >> 5, lane = gtid & 31;
    if (warp < Kq) {
        const float* row = cb + (size_t)warp * Dq;
        float s = 0.f;
#pragma unroll
        for (int d = lane; d < Dq; d += 32) { float v = row[d]; s += v * v; }
#pragma unroll
        for (int o = 16; o; o >>= 1) s += __shfl_xor_sync(0xffffffffu, s, o);
        if (lane == 0) g_c2[warp] = s;
    }
    if (gtid < Mq) g_best[gtid] = 0xFFFFFFFFFFFFFFFFULL;
}

// ---------------------------------------------------------------------------
// Fused GEMM (HMMA) + argmin.
// Grid (Mq/BM, Kq/BN) = (128, 64). 256 threads = 8 warps (4M x 2N).
// Warp tile 32M x 64N, mma m16n8k16. 3-stage cp.async pipeline, 2 CTAs/SM.
// smem: NSTAGE stages of [A: 128x128B | B: 128x128B] = 32KB each, + c2 tile.
// ---------------------------------------------------------------------------
#define STAGE_BYTES 32768
#define SMEM_TOTAL (NSTAGE * STAGE_BYTES + 512)   // 98816 -> two CTAs fit per SM

__global__ __launch_bounds__(256, 2) void vq_mma_kernel() {
    extern __shared__ char smem[];
    const uint32_t sb = smem_u32(smem);
    const int tid = threadIdx.x;
    const int wid = tid >> 5, lane = tid & 31;
    const int m0 = blockIdx.x * BM, n0 = blockIdx.y * BN;
    const int wm = wid & 3, wn = wid >> 2;

    float* c2s = (float*)(smem + NSTAGE * STAGE_BYTES);
    if (tid < BN) c2s[tid] = g_c2[n0 + tid];

    // cp.async addressing, hoisted. Each thread moves 4 A segs + 4 B segs of 16B.
    // seg i covers row rr + 32*i; since 32 == 0 mod 8, the swizzle term is
    // i-invariant: dst_i = dst0 + i*4096, src_i = src0 + i*65536.
    const int rr = tid >> 3, q = tid & 7;
    const uint32_t dA0 = rr * 128 + ((q ^ (rr & 7)) << 4);
    const char* srcA0 = (const char*)g_A + (size_t)(m0 + rr) * 2048 + q * 16;
    const char* srcB0 = (const char*)g_B + (size_t)(n0 + rr) * 2048 + q * 16;

    // ldmatrix row/seg components (swizzle: seg ^ (row & 7), row&7 == lane&7)
    const int rA = (lane & 7) + ((lane >> 3) & 1) * 8;   // A: row within 16
    const int sA = (lane >> 4) & 1;                      // A: k-seg select
    const int rB = (lane & 7) + ((lane >> 4) & 1) * 8;   // B: row within 16
    const int sB = (lane >> 3) & 1;                      // B: k-seg select
    const int l7 = lane & 7;

    uint32_t aoff[2], boff[4];
#pragma unroll
    for (int mi = 0; mi < 2; mi++) aoff[mi] = (wm * 32 + mi * 16 + rA) * 128;
#pragma unroll
    for (int nb = 0; nb < 4; nb++) boff[nb] = 16384 + (wn * 64 + nb * 16 + rB) * 128;

    float acc[2][8][4];
#pragma unroll
    for (int mi = 0; mi < 2; mi++)
#pragma unroll
        for (int nj = 0; nj < 8; nj++)
#pragma unroll
            for (int r = 0; r < 4; r++) acc[mi][nj][r] = 0.f;

    auto load_stage = [&](int t, int slot) {
        const uint32_t base = sb + slot * STAGE_BYTES;
        const char* sa = srcA0 + t * 128;
        const char* sc = srcB0 + t * 128;
#pragma unroll
        for (int i = 0; i < 4; i++) CP_ASYNC16(base + dA0 + i * 4096, sa + i * 65536);
#pragma unroll
        for (int i = 0; i < 4; i++) CP_ASYNC16(base + 16384 + dA0 + i * 4096, sc + i * 65536);
        CP_COMMIT();
    };

    load_stage(0, 0);
    load_stage(1, 1);

    int slot = 0;
    for (int t = 0; t < NITER; t++) {
        CP_WAIT(1);
        __syncthreads();
        if (t + 2 < NITER) {
            int ns = slot + 2; if (ns >= NSTAGE) ns -= NSTAGE;
            load_stage(t + 2, ns);
        }

        const uint32_t st = sb + slot * STAGE_BYTES;
        slot++; if (slot == NSTAGE) slot = 0;
#pragma unroll
        for (int ks = 0; ks < 4; ks++) {
            const uint32_t segA = (((ks * 2 + sA) ^ l7) << 4);
            const uint32_t segB = (((ks * 2 + sB) ^ l7) << 4);
            uint32_t a[2][4], b[4][4];
#pragma unroll
            for (int mi = 0; mi < 2; mi++)
                LDMATRIX_X4(a[mi][0], a[mi][1], a[mi][2], a[mi][3], st + aoff[mi] + segA);
#pragma unroll
            for (int nb = 0; nb < 4; nb++)
                LDMATRIX_X4(b[nb][0], b[nb][1], b[nb][2], b[nb][3], st + boff[nb] + segB);
#pragma unroll
            for (int mi = 0; mi < 2; mi++)
#pragma unroll
                for (int nj = 0; nj < 8; nj++)
                    MMA16816(acc[mi][nj], a[mi], b[nj >> 1][(nj & 1) * 2],
                             b[nj >> 1][(nj & 1) * 2 + 1]);
        }
    }

    // ---- fused argmin epilogue ----
    // acc[mi][nj] covers rows {wm*32+mi*16+lane/4, +8}, cols wn*64+nj*8+2*(lane&3)+{0,1}
#pragma unroll
    for (int mi = 0; mi < 2; mi++) {
#pragma unroll
        for (int h = 0; h < 2; h++) {
            float best = __int_as_float(0x7f800000);
            int bi = 0;
#pragma unroll
            for (int nj = 0; nj < 8; nj++) {
                int col = wn * 64 + nj * 8 + (lane & 3) * 2;
                float d0 = fmaf(-2.f, acc[mi][nj][h * 2 + 0], c2s[col]);
                float d1 = fmaf(-2.f, acc[mi][nj][h * 2 + 1], c2s[col + 1]);
                if (d0 < best) { best = d0; bi = col; }
                if (d1 < best) { best = d1; bi = col + 1; }
            }
            // reduce across the 4 lanes of the quad (same row)
#pragma unroll
            for (int off = 1; off <= 2; off <<= 1) {
                float od = __shfl_xor_sync(0xffffffffu, best, off);
                int oi = __shfl_xor_sync(0xffffffffu, bi, off);
                if (od < best || (od == best && oi < bi)) { best = od; bi = oi; }
            }
            if ((lane & 3) == 0) {
                int m = m0 + wm * 32 + mi * 16 + h * 8 + (lane >> 2);
                unsigned long long pk =
                    ((unsigned long long)fkey(best) << 32) | (unsigned int)(n0 + bi);
                atomicMin(&g_best[m], pk);
            }
        }
    }
}

// ---------------------------------------------------------------------------
// Gather + write tuple output: [x_recon | z_e | z_q | indices-as-float]
// ---------------------------------------------------------------------------
__global__ void gather_kernel(const float* __restrict__ x,
                              const float* __restrict__ cb,
                              float* __restrict__ out) {
    const int m = blockIdx.x;
    const int idx = (int)(g_best[m] & 0xFFFFFFFFULL);

    const float4* crow = (const float4*)(cb + (size_t)idx * Dq);
    const float4* xrow = (const float4*)(x + (size_t)m * Dq);
    const size_t BND = (size_t)Mq * Dq;
    float4* o0 = (float4*)(out) + (size_t)m * (Dq / 4);
    float4* o1 = (float4*)(out + BND) + (size_t)m * (Dq / 4);
    float4* o2 = (float4*)(out + 2 * BND) + (size_t)m * (Dq / 4);

    const int t = threadIdx.x;  // 0..63
    float4 c = crow[t];
    o0[t] = c;
    o2[t] = c;
    o1[t] = xrow[t];
    if (t == 0) out[3 * BND + m] = (float)idx;
}

// ---------------------------------------------------------------------------
extern "C" void kernel_launch(void* const* d_in, const int* in_sizes, int n_in,
                              void* d_out, int out_size) {
    const float* x = (const float*)d_in[0];    // (B, N, D) fp32
    const float* cb = (const float*)d_in[1];   // (K, D) fp32
    float* out = (float*)d_out;
    (void)in_sizes; (void)n_in; (void)out_size;

    split_x_kernel<<<Mq * Dq / 4 / 256, 256>>>(x);
    split_c_kernel<<<Kq * Dq / 4 / 256, 256>>>(cb);
    prep_c2_kernel<<<1024, 256>>>(cb);

    cudaFuncSetAttribute(vq_mma_kernel,
                         cudaFuncAttributeMaxDynamicSharedMemorySize, SMEM_TOTAL);
    dim3 grid(Mq / BM, Kq / BN);
    vq_mma_kernel<<<grid, 256, SMEM_TOTAL>>>();

    gather_kernel<<<Mq, 64>>>(x, cb, out);
}

// round 8
// speedup vs baseline: 5.4819x; 1.2819x over previous
#include <cuda_runtime.h>
#include <cuda_fp16.h>
#include <cstdint>

// Problem constants
#define Mq 16384   // B*N rows
#define Kq 8192    // codebook size
#define Dq 256     // dim
#define KP 768     // K' = 3 * Dq (3-term split: [hx,lx,hx] . [hc,hc,lc] = hh+lh+hl)

#define BM 128
#define BN 128
#define BK 64      // halves per k-iter (128 bytes per row-chunk)
#define NSTAGE 3
#define NITER (KP / BK)   // 12
#define ROWB (KP * 2)     // bytes per row = 1536

// ---------------------------------------------------------------------------
// Static device scratch (no cudaMalloc allowed)
// ---------------------------------------------------------------------------
__device__ __align__(16) __half g_A[Mq * KP];   // 24 MB
__device__ __align__(16) __half g_B[Kq * KP];   // 12 MB
__device__ float g_c2[Kq];
__device__ unsigned long long g_best[Mq];

// ---------------------------------------------------------------------------
// Helpers
// ---------------------------------------------------------------------------
__device__ __forceinline__ unsigned int fkey(float f) {
    unsigned int u = __float_as_uint(f);
    return (u & 0x80000000u) ? ~u : (u | 0x80000000u);
}
__device__ __forceinline__ uint32_t smem_u32(const void* p) {
    uint32_t a;
    asm("{ .reg .u64 t; cvta.to.shared.u64 t, %1; cvt.u32.u64 %0, t; }" : "=r"(a) : "l"(p));
    return a;
}
#define CP_ASYNC16(dst, src) \
    asm volatile("cp.async.cg.shared.global [%0], [%1], 16;" :: "r"(dst), "l"(src))
#define CP_COMMIT() asm volatile("cp.async.commit_group;")
#define CP_WAIT(n)  asm volatile("cp.async.wait_group %0;" :: "n"(n))

#define LDMATRIX_X4(r0, r1, r2, r3, addr)                                     \
    asm volatile("ldmatrix.sync.aligned.m8n8.x4.shared.b16 {%0,%1,%2,%3}, [%4];" \
                 : "=r"(r0), "=r"(r1), "=r"(r2), "=r"(r3) : "r"(addr))

#define MMA16816(c, a, b0, b1)                                                \
    asm volatile(                                                             \
        "mma.sync.aligned.m16n8k16.row.col.f32.f16.f16.f32 "                  \
        "{%0,%1,%2,%3}, {%4,%5,%6,%7}, {%8,%9}, {%0,%1,%2,%3};"               \
        : "+f"((c)[0]), "+f"((c)[1]), "+f"((c)[2]), "+f"((c)[3])              \
        : "r"((a)[0]), "r"((a)[1]), "r"((a)[2]), "r"((a)[3]), "r"(b0), "r"(b1))

// ---------------------------------------------------------------------------
// Prep: split fp32 -> fp16 hi/lo, laid out as K'-concat rows (3-term).
// A'[m] = [hx(256) | lx | hx],  B'[k] = [hc | hc | lc]
// dot(A',B') = hh + lh + hl  (ll term dropped; ~2.6e-6 distance noise)
// ---------------------------------------------------------------------------
__device__ __forceinline__ void split4(const float4 v, uint2& hp, uint2& lp) {
    float f[4] = {v.x, v.y, v.z, v.w};
    __half h[4], l[4];
#pragma unroll
    for (int j = 0; j < 4; j++) {
        h[j] = __float2half_rn(f[j]);
        l[j] = __float2half_rn(f[j] - __half2float(h[j]));
    }
    __half2 h01 = __halves2half2(h[0], h[1]), h23 = __halves2half2(h[2], h[3]);
    __half2 l01 = __halves2half2(l[0], l[1]), l23 = __halves2half2(l[2], l[3]);
    hp.x = *reinterpret_cast<uint32_t*>(&h01); hp.y = *reinterpret_cast<uint32_t*>(&h23);
    lp.x = *reinterpret_cast<uint32_t*>(&l01); lp.y = *reinterpret_cast<uint32_t*>(&l23);
}

__global__ void split_x_kernel(const float* __restrict__ x) {
    int i = blockIdx.x * 256 + threadIdx.x;      // over Mq*Dq/4
    int m = i >> 6, j = i & 63;                  // j: uint2 index within 256-half section
    uint2 hp, lp;
    split4(((const float4*)x)[i], hp, lp);
    uint2* pA = (uint2*)g_A + (size_t)m * 192;   // 768 halves = 192 uint2 per row
    pA[j] = hp; pA[64 + j] = lp; pA[128 + j] = hp;
}

__global__ void split_c_kernel(const float* __restrict__ cb) {
    int i = blockIdx.x * 256 + threadIdx.x;      // over Kq*Dq/4
    int k = i >> 6, j = i & 63;
    uint2 hp, lp;
    split4(((const float4*)cb)[i], hp, lp);
    uint2* pB = (uint2*)g_B + (size_t)k * 192;
    pB[j] = hp; pB[64 + j] = hp; pB[128 + j] = lp;
}

// c2[k] = ||c_k||^2 (warp per code) + re-init g_best every launch (graph replay)
__global__ void prep_c2_kernel(const float* __restrict__ cb) {
    int gtid = blockIdx.x * blockDim.x + threadIdx.x;
    int warp = gtid >> 5, lane = gtid & 31;
    if (warp < Kq) {
        const float* row = cb + (size_t)warp * Dq;
        float s = 0.f;
#pragma unroll
        for (int d = lane; d < Dq; d += 32) { float v = row[d]; s += v * v; }
#pragma unroll
        for (int o = 16; o; o >>= 1) s += __shfl_xor_sync(0xffffffffu, s, o);
        if (lane == 0) g_c2[warp] = s;
    }
    if (gtid < Mq) g_best[gtid] = 0xFFFFFFFFFFFFFFFFULL;
}

// ---------------------------------------------------------------------------
// Fused GEMM (HMMA) + argmin.
// Grid (Mq/BM, Kq/BN) = (128, 64). 256 threads = 8 warps (4M x 2N).
// Warp tile 32M x 64N, mma m16n8k16. 3-stage cp.async pipeline, 2 CTAs/SM.
// smem: NSTAGE stages of [A: 128x128B | B: 128x128B] = 32KB each, + c2 tile.
// ---------------------------------------------------------------------------
#define STAGE_BYTES 32768
#define SMEM_TOTAL (NSTAGE * STAGE_BYTES + 512)   // 98816 -> two CTAs fit per SM

__global__ __launch_bounds__(256, 2) void vq_mma_kernel() {
    extern __shared__ char smem[];
    const uint32_t sb = smem_u32(smem);
    const int tid = threadIdx.x;
    const int wid = tid >> 5, lane = tid & 31;
    const int m0 = blockIdx.x * BM, n0 = blockIdx.y * BN;
    const int wm = wid & 3, wn = wid >> 2;

    float* c2s = (float*)(smem + NSTAGE * STAGE_BYTES);
    if (tid < BN) c2s[tid] = g_c2[n0 + tid];

    // cp.async addressing, hoisted. Each thread moves 4 A segs + 4 B segs of 16B.
    // seg i covers row rr + 32*i; since 32 == 0 mod 8, the swizzle term is
    // i-invariant: dst_i = dst0 + i*4096, src_i = src0 + i*32*ROWB.
    const int rr = tid >> 3, q = tid & 7;
    const uint32_t dA0 = rr * 128 + ((q ^ (rr & 7)) << 4);
    const char* srcA0 = (const char*)g_A + (size_t)(m0 + rr) * ROWB + q * 16;
    const char* srcB0 = (const char*)g_B + (size_t)(n0 + rr) * ROWB + q * 16;

    // ldmatrix row/seg components (swizzle: seg ^ (row & 7), row&7 == lane&7)
    const int rA = (lane & 7) + ((lane >> 3) & 1) * 8;   // A: row within 16
    const int sA = (lane >> 4) & 1;                      // A: k-seg select
    const int rB = (lane & 7) + ((lane >> 4) & 1) * 8;   // B: row within 16
    const int sB = (lane >> 3) & 1;                      // B: k-seg select
    const int l7 = lane & 7;

    uint32_t aoff[2], boff[4];
#pragma unroll
    for (int mi = 0; mi < 2; mi++) aoff[mi] = (wm * 32 + mi * 16 + rA) * 128;
#pragma unroll
    for (int nb = 0; nb < 4; nb++) boff[nb] = 16384 + (wn * 64 + nb * 16 + rB) * 128;

    float acc[2][8][4];
#pragma unroll
    for (int mi = 0; mi < 2; mi++)
#pragma unroll
        for (int nj = 0; nj < 8; nj++)
#pragma unroll
            for (int r = 0; r < 4; r++) acc[mi][nj][r] = 0.f;

    auto load_stage = [&](int t, int slot) {
        const uint32_t base = sb + slot * STAGE_BYTES;
        const char* sa = srcA0 + t * 128;
        const char* sc = srcB0 + t * 128;
#pragma unroll
        for (int i = 0; i < 4; i++) CP_ASYNC16(base + dA0 + i * 4096, sa + i * (size_t)(32 * ROWB));
#pragma unroll
        for (int i = 0; i < 4; i++) CP_ASYNC16(base + 16384 + dA0 + i * 4096, sc + i * (size_t)(32 * ROWB));
        CP_COMMIT();
    };

    load_stage(0, 0);
    load_stage(1, 1);

    int slot = 0;
    for (int t = 0; t < NITER; t++) {
        CP_WAIT(1);
        __syncthreads();
        if (t + 2 < NITER) {
            int ns = slot + 2; if (ns >= NSTAGE) ns -= NSTAGE;
            load_stage(t + 2, ns);
        }

        const uint32_t st = sb + slot * STAGE_BYTES;
        slot++; if (slot == NSTAGE) slot = 0;
#pragma unroll
        for (int ks = 0; ks < 4; ks++) {
            const uint32_t segA = (((ks * 2 + sA) ^ l7) << 4);
            const uint32_t segB = (((ks * 2 + sB) ^ l7) << 4);
            uint32_t a[2][4], b[4][4];
#pragma unroll
            for (int mi = 0; mi < 2; mi++)
                LDMATRIX_X4(a[mi][0], a[mi][1], a[mi][2], a[mi][3], st + aoff[mi] + segA);
#pragma unroll
            for (int nb = 0; nb < 4; nb++)
                LDMATRIX_X4(b[nb][0], b[nb][1], b[nb][2], b[nb][3], st + boff[nb] + segB);
#pragma unroll
            for (int mi = 0; mi < 2; mi++)
#pragma unroll
                for (int nj = 0; nj < 8; nj++)
                    MMA16816(acc[mi][nj], a[mi], b[nj >> 1][(nj & 1) * 2],
                             b[nj >> 1][(nj & 1) * 2 + 1]);
        }
    }

    // ---- fused argmin epilogue ----
    // acc[mi][nj] covers rows {wm*32+mi*16+lane/4, +8}, cols wn*64+nj*8+2*(lane&3)+{0,1}
#pragma unroll
    for (int mi = 0; mi < 2; mi++) {
#pragma unroll
        for (int h = 0; h < 2; h++) {
            float best = __int_as_float(0x7f800000);
            int bi = 0;
#pragma unroll
            for (int nj = 0; nj < 8; nj++) {
                int col = wn * 64 + nj * 8 + (lane & 3) * 2;
                float d0 = fmaf(-2.f, acc[mi][nj][h * 2 + 0], c2s[col]);
                float d1 = fmaf(-2.f, acc[mi][nj][h * 2 + 1], c2s[col + 1]);
                if (d0 < best) { best = d0; bi = col; }
                if (d1 < best) { best = d1; bi = col + 1; }
            }
            // reduce across the 4 lanes of the quad (same row)
#pragma unroll
            for (int off = 1; off <= 2; off <<= 1) {
                float od = __shfl_xor_sync(0xffffffffu, best, off);
                int oi = __shfl_xor_sync(0xffffffffu, bi, off);
                if (od < best || (od == best && oi < bi)) { best = od; bi = oi; }
            }
            if ((lane & 3) == 0) {
                int m = m0 + wm * 32 + mi * 16 + h * 8 + (lane >> 2);
                unsigned long long pk =
                    ((unsigned long long)fkey(best) << 32) | (unsigned int)(n0 + bi);
                atomicMin(&g_best[m], pk);
            }
        }
    }
}

// ---------------------------------------------------------------------------
// Gather + write tuple output: [x_recon | z_e | z_q | indices-as-float]
// ---------------------------------------------------------------------------
__global__ void gather_kernel(const float* __restrict__ x,
                              const float* __restrict__ cb,
                              float* __restrict__ out) {
    const int m = blockIdx.x;
    const int idx = (int)(g_best[m] & 0xFFFFFFFFULL);

    const float4* crow = (const float4*)(cb + (size_t)idx * Dq);
    const float4* xrow = (const float4*)(x + (size_t)m * Dq);
    const size_t BND = (size_t)Mq * Dq;
    float4* o0 = (float4*)(out) + (size_t)m * (Dq / 4);
    float4* o1 = (float4*)(out + BND) + (size_t)m * (Dq / 4);
    float4* o2 = (float4*)(out + 2 * BND) + (size_t)m * (Dq / 4);

    const int t = threadIdx.x;  // 0..63
    float4 c = crow[t];
    o0[t] = c;
    o2[t] = c;
    o1[t] = xrow[t];
    if (t == 0) out[3 * BND + m] = (float)idx;
}

// ---------------------------------------------------------------------------
extern "C" void kernel_launch(void* const* d_in, const int* in_sizes, int n_in,
                              void* d_out, int out_size) {
    const float* x = (const float*)d_in[0];    // (B, N, D) fp32
    const float* cb = (const float*)d_in[1];   // (K, D) fp32
    float* out = (float*)d_out;
    (void)in_sizes; (void)n_in; (void)out_size;

    split_x_kernel<<<Mq * Dq / 4 / 256, 256>>>(x);
    split_c_kernel<<<Kq * Dq / 4 / 256, 256>>>(cb);
    prep_c2_kernel<<<1024, 256>>>(cb);

    cudaFuncSetAttribute(vq_mma_kernel,
                         cudaFuncAttributeMaxDynamicSharedMemorySize, SMEM_TOTAL);
    dim3 grid(Mq / BM, Kq / BN);
    vq_mma_kernel<<<grid, 256, SMEM_TOTAL>>>();

    gather_kernel<<<Mq, 64>>>(x, cb, out);
}

// round 13
// speedup vs baseline: 7.7026x; 1.4051x over previous
#include <cuda_runtime.h>
#include <cuda_fp16.h>
#include <cstdint>

// Problem constants
#define Mq 16384   // B*N rows
#define Kq 8192    // codebook size
#define Dq 256     // dim

#define BM 128
#define BN 128
#define BK 64      // halves per k-iter (128 bytes per row-chunk)
#define NSTAGE 3
#define NITER (Dq / BK)   // 4  (hh term only)
#define ROWB (Dq * 2)     // bytes per fp16 row = 512

#define T_PUSH 2.0f       // certified candidate margin (hard bound ~1.57)
#define CAND_CAP 256

// ---------------------------------------------------------------------------
// Static device scratch (no cudaMalloc allowed)
// ---------------------------------------------------------------------------
__device__ __align__(16) __half g_A[Mq * Dq];   // 8 MB  (hx)
__device__ __align__(16) __half g_B[Kq * Dq];   // 4 MB  (hc)
__device__ float g_c2[Kq];
__device__ int g_ccount[Mq];
__device__ uint2 g_cand[Mq * CAND_CAP];          // (d~ bits, k) 32 MB
__device__ int g_idx[Mq];

// ---------------------------------------------------------------------------
// Helpers
// ---------------------------------------------------------------------------
__device__ __forceinline__ uint32_t smem_u32(const void* p) {
    uint32_t a;
    asm("{ .reg .u64 t; cvta.to.shared.u64 t, %1; cvt.u32.u64 %0, t; }" : "=r"(a) : "l"(p));
    return a;
}
#define CP_ASYNC16(dst, src) \
    asm volatile("cp.async.cg.shared.global [%0], [%1], 16;" :: "r"(dst), "l"(src))
#define CP_COMMIT() asm volatile("cp.async.commit_group;")
#define CP_WAIT(n)  asm volatile("cp.async.wait_group %0;" :: "n"(n))

#define LDMATRIX_X4(r0, r1, r2, r3, addr)                                     \
    asm volatile("ldmatrix.sync.aligned.m8n8.x4.shared.b16 {%0,%1,%2,%3}, [%4];" \
                 : "=r"(r0), "=r"(r1), "=r"(r2), "=r"(r3) : "r"(addr))

#define MMA16816(c, a, b0, b1)                                                \
    asm volatile(                                                             \
        "mma.sync.aligned.m16n8k16.row.col.f32.f16.f16.f32 "                  \
        "{%0,%1,%2,%3}, {%4,%5,%6,%7}, {%8,%9}, {%0,%1,%2,%3};"               \
        : "+f"((c)[0]), "+f"((c)[1]), "+f"((c)[2]), "+f"((c)[3])              \
        : "r"((a)[0]), "r"((a)[1]), "r"((a)[2]), "r"((a)[3]), "r"(b0), "r"(b1))

// ---------------------------------------------------------------------------
// Prep: fp16 hi parts only
// ---------------------------------------------------------------------------
__device__ __forceinline__ uint2 hi4(const float4 v) {
    __half2 h01 = __halves2half2(__float2half_rn(v.x), __float2half_rn(v.y));
    __half2 h23 = __halves2half2(__float2half_rn(v.z), __float2half_rn(v.w));
    uint2 r;
    r.x = *reinterpret_cast<uint32_t*>(&h01);
    r.y = *reinterpret_cast<uint32_t*>(&h23);
    return r;
}

__global__ void split_x_kernel(const float* __restrict__ x) {
    int i = blockIdx.x * 256 + threadIdx.x;       // over Mq*Dq/4
    ((uint2*)g_A)[i] = hi4(((const float4*)x)[i]);
}

__global__ void split_c_kernel(const float* __restrict__ cb) {
    int i = blockIdx.x * 256 + threadIdx.x;       // over Kq*Dq/4
    ((uint2*)g_B)[i] = hi4(((const float4*)cb)[i]);
}

// c2[k] = ||c_k||^2 (warp per code) + zero candidate counters (every launch)
__global__ void prep_c2_kernel(const float* __restrict__ cb) {
    int gtid = blockIdx.x * blockDim.x + threadIdx.x;
    int warp = gtid >> 5, lane = gtid & 31;
    if (warp < Kq) {
        const float* row = cb + (size_t)warp * Dq;
        float s = 0.f;
#pragma unroll
        for (int d = lane; d < Dq; d += 32) { float v = row[d]; s += v * v; }
#pragma unroll
        for (int o = 16; o; o >>= 1) s += __shfl_xor_sync(0xffffffffu, s, o);
        if (lane == 0) g_c2[warp] = s;
    }
    if (gtid < Mq) g_ccount[gtid] = 0;
}

// ---------------------------------------------------------------------------
// Phase 1: hh-GEMM (HMMA) + candidate push.
// Grid (Mq/BM, Kq/BN) = (128, 64). 256 threads = 8 warps (4M x 2N).
// Push threshold = CTA-wide per-row min + T (the two N-warps exchange their
// per-row local minima through smem), so guaranteed pushes = 1 per (row, CTA).
// ---------------------------------------------------------------------------
#define STAGE_BYTES 32768
// [stages | c2 tile 512B | rowmin 128*2 floats = 1KB]
#define SMEM_TOTAL (NSTAGE * STAGE_BYTES + 512 + 1024)

__global__ __launch_bounds__(256, 2) void vq_mma_kernel() {
    extern __shared__ char smem[];
    const uint32_t sb = smem_u32(smem);
    const int tid = threadIdx.x;
    const int wid = tid >> 5, lane = tid & 31;
    const int m0 = blockIdx.x * BM, n0 = blockIdx.y * BN;
    const int wm = wid & 3, wn = wid >> 2;

    float* c2s = (float*)(smem + NSTAGE * STAGE_BYTES);
    float* rowmin = (float*)(smem + NSTAGE * STAGE_BYTES + 512);  // [128][2]
    if (tid < BN) c2s[tid] = g_c2[n0 + tid];

    // cp.async addressing (hoisted; swizzle i-invariant since rows step by 32)
    const int rr = tid >> 3, q = tid & 7;
    const uint32_t dA0 = rr * 128 + ((q ^ (rr & 7)) << 4);
    const char* srcA0 = (const char*)g_A + (size_t)(m0 + rr) * ROWB + q * 16;
    const char* srcB0 = (const char*)g_B + (size_t)(n0 + rr) * ROWB + q * 16;

    const int rA = (lane & 7) + ((lane >> 3) & 1) * 8;
    const int sA = (lane >> 4) & 1;
    const int rB = (lane & 7) + ((lane >> 4) & 1) * 8;
    const int sB = (lane >> 3) & 1;
    const int l7 = lane & 7;

    uint32_t aoff[2], boff[4];
#pragma unroll
    for (int mi = 0; mi < 2; mi++) aoff[mi] = (wm * 32 + mi * 16 + rA) * 128;
#pragma unroll
    for (int nb = 0; nb < 4; nb++) boff[nb] = 16384 + (wn * 64 + nb * 16 + rB) * 128;

    float acc[2][8][4];
#pragma unroll
    for (int mi = 0; mi < 2; mi++)
#pragma unroll
        for (int nj = 0; nj < 8; nj++)
#pragma unroll
            for (int r = 0; r < 4; r++) acc[mi][nj][r] = 0.f;

    auto load_stage = [&](int t, int slot) {
        const uint32_t base = sb + slot * STAGE_BYTES;
        const char* sa = srcA0 + t * 128;
        const char* sc = srcB0 + t * 128;
#pragma unroll
        for (int i = 0; i < 4; i++) CP_ASYNC16(base + dA0 + i * 4096, sa + i * (size_t)(32 * ROWB));
#pragma unroll
        for (int i = 0; i < 4; i++) CP_ASYNC16(base + 16384 + dA0 + i * 4096, sc + i * (size_t)(32 * ROWB));
        CP_COMMIT();
    };

    load_stage(0, 0);
    load_stage(1, 1);

    int slot = 0;
    for (int t = 0; t < NITER; t++) {
        CP_WAIT(1);
        __syncthreads();
        if (t + 2 < NITER) {
            int ns = slot + 2; if (ns >= NSTAGE) ns -= NSTAGE;
            load_stage(t + 2, ns);
        }

        const uint32_t st = sb + slot * STAGE_BYTES;
        slot++; if (slot == NSTAGE) slot = 0;
#pragma unroll
        for (int ks = 0; ks < 4; ks++) {
            const uint32_t segA = (((ks * 2 + sA) ^ l7) << 4);
            const uint32_t segB = (((ks * 2 + sB) ^ l7) << 4);
            uint32_t a[2][4], b[4][4];
#pragma unroll
            for (int mi = 0; mi < 2; mi++)
                LDMATRIX_X4(a[mi][0], a[mi][1], a[mi][2], a[mi][3], st + aoff[mi] + segA);
#pragma unroll
            for (int nb = 0; nb < 4; nb++)
                LDMATRIX_X4(b[nb][0], b[nb][1], b[nb][2], b[nb][3], st + boff[nb] + segB);
#pragma unroll
            for (int mi = 0; mi < 2; mi++)
#pragma unroll
                for (int nj = 0; nj < 8; nj++)
                    MMA16816(acc[mi][nj], a[mi], b[nj >> 1][(nj & 1) * 2],
                             b[nj >> 1][(nj & 1) * 2 + 1]);
        }
    }

    // ---- epilogue pass 1: per-warp per-row local min -> smem ----
    // acc[mi][nj] covers rows {wm*32+mi*16+lane/4, +8}, cols wn*64+nj*8+2*(lane&3)+{0,1}
#pragma unroll
    for (int mi = 0; mi < 2; mi++) {
#pragma unroll
        for (int h = 0; h < 2; h++) {
            float lmin = __int_as_float(0x7f800000);
#pragma unroll
            for (int nj = 0; nj < 8; nj++) {
                int col = wn * 64 + nj * 8 + (lane & 3) * 2;
                float d0 = fmaf(-2.f, acc[mi][nj][h * 2 + 0], c2s[col]);
                float d1 = fmaf(-2.f, acc[mi][nj][h * 2 + 1], c2s[col + 1]);
                lmin = fminf(lmin, fminf(d0, d1));
            }
#pragma unroll
            for (int off = 1; off <= 2; off <<= 1)
                lmin = fminf(lmin, __shfl_xor_sync(0xffffffffu, lmin, off));
            if ((lane & 3) == 0) {
                int rl = wm * 32 + mi * 16 + h * 8 + (lane >> 2);
                rowmin[rl * 2 + wn] = lmin;
            }
        }
    }
    __syncthreads();

    // ---- epilogue pass 2: push candidates vs CTA-wide row min + T ----
#pragma unroll
    for (int mi = 0; mi < 2; mi++) {
#pragma unroll
        for (int h = 0; h < 2; h++) {
            const int rl = wm * 32 + mi * 16 + h * 8 + (lane >> 2);
            const float thr = fminf(rowmin[rl * 2], rowmin[rl * 2 + 1]) + T_PUSH;
            const int m = m0 + rl;
#pragma unroll
            for (int nj = 0; nj < 8; nj++) {
#pragma unroll
                for (int e = 0; e < 2; e++) {
                    float d = fmaf(-2.f, acc[mi][nj][h * 2 + e],
                                   c2s[wn * 64 + nj * 8 + (lane & 3) * 2 + e]);
                    if (d <= thr) {
                        int k = n0 + wn * 64 + nj * 8 + (lane & 3) * 2 + e;
                        int pos = atomicAdd(&g_ccount[m], 1);
                        if (pos < CAND_CAP) {
                            g_cand[m * CAND_CAP + pos] =
                                make_uint2(__float_as_uint(d), (unsigned)k);
                        }
                    }
                }
            }
        }
    }
}

// ---------------------------------------------------------------------------
// Phase 2: resolve. One warp per row. Normal path: global d~min over
// candidates, exact fp32 rescore of those within T, min (tie -> lowest k).
// Overflow path (cnt > CAND_CAP, i.e. pushes were dropped): exact full scan
// over all Kq codes -- correctness never depends on the capacity model.
// ---------------------------------------------------------------------------
__global__ __launch_bounds__(256) void resolve_kernel(const float* __restrict__ x,
                                                      const float* __restrict__ cb) {
    __shared__ float sx[8][Dq];   // x rows cached for the (rare) overflow path
    const int warp = (blockIdx.x * 256 + threadIdx.x) >> 5;
    const int wloc = (threadIdx.x >> 5);
    const int lane = threadIdx.x & 31;
    if (warp >= Mq) return;
    const int m = warp;

    // x row resident in registers (8 per lane), and in smem for overflow path
    float xr[8];
#pragma unroll
    for (int j = 0; j < 8; j++) {
        xr[j] = x[(size_t)m * Dq + lane + 32 * j];
        sx[wloc][lane + 32 * j] = xr[j];
    }

    const int rawcnt = g_ccount[m];
    float bestd = __int_as_float(0x7f800000);
    int bestk = Kq;

    if (rawcnt <= CAND_CAP) {
        // ---- fast path: candidate list is complete ----
        float dmin = __int_as_float(0x7f800000);
        for (int i = lane; i < rawcnt; i += 32)
            dmin = fminf(dmin, __uint_as_float(g_cand[m * CAND_CAP + i].x));
#pragma unroll
        for (int o = 16; o; o >>= 1)
            dmin = fminf(dmin, __shfl_xor_sync(0xffffffffu, dmin, o));
        const float thr = dmin + T_PUSH;

        for (int i = 0; i < rawcnt; i++) {
            uint2 ent = g_cand[m * CAND_CAP + i];   // warp-uniform broadcast load
            if (__uint_as_float(ent.x) > thr) continue;
            int k = (int)ent.y;
            const float* crow = cb + (size_t)k * Dq;
            float s = 0.f;
#pragma unroll
            for (int j = 0; j < 8; j++) s += xr[j] * crow[lane + 32 * j];
#pragma unroll
            for (int o = 16; o; o >>= 1) s += __shfl_xor_sync(0xffffffffu, s, o);
            float d = fmaf(-2.f, s, g_c2[k]);       // uniform across lanes
            if (d < bestd || (d == bestd && k < bestk)) { bestd = d; bestk = k; }
        }
    } else {
        // ---- overflow fallback: exact scan of all codes (lane-parallel) ----
        for (int k = lane; k < Kq; k += 32) {
            const float* crow = cb + (size_t)k * Dq;
            float s = 0.f;
#pragma unroll 8
            for (int d = 0; d < Dq; d++) s += sx[wloc][d] * crow[d];
            float dd = fmaf(-2.f, s, g_c2[k]);
            if (dd < bestd || (dd == bestd && k < bestk)) { bestd = dd; bestk = k; }
        }
#pragma unroll
        for (int o = 16; o; o >>= 1) {
            float od = __shfl_xor_sync(0xffffffffu, bestd, o);
            int ok = __shfl_xor_sync(0xffffffffu, bestk, o);
            if (od < bestd || (od == bestd && ok < bestk)) { bestd = od; bestk = ok; }
        }
    }
    if (lane == 0) g_idx[m] = bestk;
}

// ---------------------------------------------------------------------------
// Gather + write tuple output: [x_recon | z_e | z_q | indices-as-float]
// ---------------------------------------------------------------------------
__global__ void gather_kernel(const float* __restrict__ x,
                              const float* __restrict__ cb,
                              float* __restrict__ out) {
    const int m = blockIdx.x;
    const int idx = g_idx[m];

    const float4* crow = (const float4*)(cb + (size_t)idx * Dq);
    const float4* xrow = (const float4*)(x + (size_t)m * Dq);
    const size_t BND = (size_t)Mq * Dq;
    float4* o0 = (float4*)(out) + (size_t)m * (Dq / 4);
    float4* o1 = (float4*)(out + BND) + (size_t)m * (Dq / 4);
    float4* o2 = (float4*)(out + 2 * BND) + (size_t)m * (Dq / 4);

    const int t = threadIdx.x;  // 0..63
    float4 c = crow[t];
    o0[t] = c;
    o2[t] = c;
    o1[t] = xrow[t];
    if (t == 0) out[3 * BND + m] = (float)idx;
}

// ---------------------------------------------------------------------------
extern "C" void kernel_launch(void* const* d_in, const int* in_sizes, int n_in,
                              void* d_out, int out_size) {
    const float* x = (const float*)d_in[0];    // (B, N, D) fp32
    const float* cb = (const float*)d_in[1];   // (K, D) fp32
    float* out = (float*)d_out;
    (void)in_sizes; (void)n_in; (void)out_size;

    split_x_kernel<<<Mq * Dq / 4 / 256, 256>>>(x);
    split_c_kernel<<<Kq * Dq / 4 / 256, 256>>>(cb);
    prep_c2_kernel<<<1024, 256>>>(cb);

    cudaFuncSetAttribute(vq_mma_kernel,
                         cudaFuncAttributeMaxDynamicSharedMemorySize, SMEM_TOTAL);
    dim3 grid(Mq / BM, Kq / BN);
    vq_mma_kernel<<<grid, 256, SMEM_TOTAL>>>();

    resolve_kernel<<<(Mq * 32 + 255) / 256, 256>>>(x, cb);
    gather_kernel<<<Mq, 64>>>(x, cb, out);
}